// round 2
// baseline (speedup 1.0000x reference)
#include <cuda_runtime.h>
#include <cstdint>

#define B_ 8
#define N_ 65536
#define C_ 64
#define M_ 64
#define CHUNKS 64
#define PTS (N_/CHUNKS)      // 1024 points per block
#define G_ 64                // points staged per group
#define NGROUPS (PTS/G_)     // 16
#define S_ 65                // padded stride for basis in shared
#define TWO_PI 6.28318530717958647692f

// Scratch (static device globals -- no allocation at runtime)
__device__ float g_part[(size_t)B_*CHUNKS*2*M_*C_];   // per-(b,chunk) partial sums [cos|sin][m][c]
__device__ float g_mixed[(size_t)B_*2*M_*C_];         // mixed coefficients [re|im][m][c]

// Generate basis (cos/sin of 2*pi*(kx*x + ky*y)) for one point into shared.
// Uses integer-lattice structure: powers of e^{i2pi x}, e^{i2pi y} via complex
// multiplies -> only 2 sincos per point instead of 64.
__device__ __forceinline__ void gen_basis(
    const float* __restrict__ cob, int base, int p,
    const int* __restrict__ kxS, const int* __restrict__ kyS,
    float* __restrict__ cosS, float* __restrict__ sinS)
{
    float2 xy = ((const float2*)cob)[base + p];
    float sx, cx, sy, cy;
    sincosf(TWO_PI * xy.x, &sx, &cx);
    sincosf(TWO_PI * xy.y, &sy, &cy);
    float pxr[7], pxi[7], pyr[7], pyi[7];
    pxr[0] = 1.f; pxi[0] = 0.f; pyr[0] = 1.f; pyi[0] = 0.f;
#pragma unroll
    for (int k = 1; k < 7; k++) {
        pxr[k] = pxr[k-1]*cx - pxi[k-1]*sx;
        pxi[k] = pxr[k-1]*sx + pxi[k-1]*cx;
        pyr[k] = pyr[k-1]*cy - pyi[k-1]*sy;
        pyi[k] = pyr[k-1]*sy + pyi[k-1]*cy;
    }
#pragma unroll 8
    for (int m = 0; m < M_; m++) {
        int kx = kxS[m], ky = kyS[m];
        int ax = kx < 0 ? -kx : kx;
        int ay = ky < 0 ? -ky : ky;
        float xr = pxr[ax], xi = (kx < 0) ? -pxi[ax] : pxi[ax];
        float yr = pyr[ay], yi = (ky < 0) ? -pyi[ay] : pyi[ay];
        cosS[p*S_ + m] = xr*yr - xi*yi;   // cos(phi)
        sinS[p*S_ + m] = xr*yi + xi*yr;   // sin(phi)
    }
}

// Pass 1: partial sums  sumC[m][c] = sum_p cos(phi)*x[p][c],  sumS[m][c] = sum_p sin(phi)*x[p][c]
// Thread tile: (tx: 4 modes) x (ty: 4 channels), 2 accumulator sets.
__global__ void __launch_bounds__(256) pass1_kernel(
    const float* __restrict__ inputs,
    const float* __restrict__ coords,
    const float* __restrict__ freq)
{
    __shared__ float cosS[G_*S_];
    __shared__ float sinS[G_*S_];
    __shared__ int kxS[M_], kyS[M_];

    int b = blockIdx.y, chunk = blockIdx.x;
    int tid = threadIdx.x;
    int tx = tid & 15, ty = tid >> 4;

    if (tid < M_) {
        kxS[tid] = (int)lrintf(freq[2*tid]);
        kyS[tid] = (int)lrintf(freq[2*tid+1]);
    }

    float accC[4][4] = {}, accSn[4][4] = {};
    const float* inb = inputs + (size_t)b*N_*C_;
    const float* cob = coords + (size_t)b*N_*2;
    int n0 = chunk * PTS;

    for (int g = 0; g < NGROUPS; g++) {
        int base = n0 + g*G_;
        __syncthreads();   // all readers done with previous group's basis
        if (tid < G_) gen_basis(cob, base, tid, kxS, kyS, cosS, sinS);
        __syncthreads();
#pragma unroll 2
        for (int p = 0; p < G_; p++) {
            float4 xv = *(const float4*)(inb + (size_t)(base + p)*C_ + 4*ty);
            float cv[4], sv[4];
#pragma unroll
            for (int i = 0; i < 4; i++) {
                cv[i] = cosS[p*S_ + 4*tx + i];
                sv[i] = sinS[p*S_ + 4*tx + i];
            }
            float xa[4] = {xv.x, xv.y, xv.z, xv.w};
#pragma unroll
            for (int i = 0; i < 4; i++)
#pragma unroll
                for (int j = 0; j < 4; j++) {
                    accC[i][j]  = fmaf(cv[i], xa[j], accC[i][j]);
                    accSn[i][j] = fmaf(sv[i], xa[j], accSn[i][j]);
                }
        }
    }

    float* pc = g_part + (size_t)(b*CHUNKS + chunk)*2*M_*C_;
#pragma unroll
    for (int i = 0; i < 4; i++)
#pragma unroll
        for (int j = 0; j < 4; j++) {
            int m = 4*tx + i, c = 4*ty + j;
            pc[m*C_ + c]           = accC[i][j];
            pc[M_*C_ + m*C_ + c]   = accSn[i][j];
        }
}

// Mix: reduce partials over chunks, normalize by N, apply complex weight.
// coeffs = (sumC - i*sumS)/N ;  mixed = coeffs * (wr + i*wi)
__global__ void mix_kernel(const float* __restrict__ wre, const float* __restrict__ wim)
{
    int idx = blockIdx.x*blockDim.x + threadIdx.x;
    if (idx >= B_*M_*C_) return;
    int mc = idx & (M_*C_ - 1);
    int b  = idx >> 12;
    const float* p = g_part + (size_t)b*CHUNKS*2*M_*C_ + mc;
    float sc = 0.f, ss = 0.f;
#pragma unroll 4
    for (int k = 0; k < CHUNKS; k++) {
        sc += p[(size_t)k*2*M_*C_];
        ss += p[(size_t)k*2*M_*C_ + M_*C_];
    }
    const float invN = 1.0f / (float)N_;
    float re = sc * invN, im = -ss * invN;
    float wr = wre[mc], wi = wim[mc];
    g_mixed[(size_t)b*2*M_*C_ + mc]           = re*wr - im*wi;
    g_mixed[(size_t)b*2*M_*C_ + M_*C_ + mc]   = re*wi + im*wr;
}

// Pass 2: out[n][c] = sum_m cos(phi)*mixed_re[m][c] - sin(phi)*mixed_im[m][c]
// Thread tile: (tx: 4 points) x (ty: 4 channels). mixed read through L1 (broadcast).
__global__ void __launch_bounds__(256) pass2_kernel(
    const float* __restrict__ coords,
    const float* __restrict__ freq,
    float* __restrict__ out)
{
    __shared__ float cosS[G_*S_];
    __shared__ float sinS[G_*S_];
    __shared__ int kxS[M_], kyS[M_];

    int b = blockIdx.y, chunk = blockIdx.x;
    int tid = threadIdx.x;
    int tx = tid & 15, ty = tid >> 4;

    if (tid < M_) {
        kxS[tid] = (int)lrintf(freq[2*tid]);
        kyS[tid] = (int)lrintf(freq[2*tid+1]);
    }

    const float* cob  = coords + (size_t)b*N_*2;
    const float* mrB  = g_mixed + (size_t)b*2*M_*C_;
    const float* miB  = mrB + M_*C_;
    float* outb = out + (size_t)b*N_*C_;
    int n0 = chunk * PTS;

    for (int g = 0; g < NGROUPS; g++) {
        int base = n0 + g*G_;
        __syncthreads();
        if (tid < G_) gen_basis(cob, base, tid, kxS, kyS, cosS, sinS);
        __syncthreads();

        float acc[4][4] = {};
#pragma unroll 2
        for (int m = 0; m < M_; m++) {
            float4 mr = *(const float4*)(mrB + m*C_ + 4*ty);
            float4 mi = *(const float4*)(miB + m*C_ + 4*ty);
            float cv[4], sv[4];
#pragma unroll
            for (int i = 0; i < 4; i++) {
                cv[i] = cosS[(4*tx + i)*S_ + m];
                sv[i] = sinS[(4*tx + i)*S_ + m];
            }
            float mra[4] = {mr.x, mr.y, mr.z, mr.w};
            float mia[4] = {mi.x, mi.y, mi.z, mi.w};
#pragma unroll
            for (int i = 0; i < 4; i++)
#pragma unroll
                for (int j = 0; j < 4; j++) {
                    acc[i][j] = fmaf( cv[i], mra[j], acc[i][j]);
                    acc[i][j] = fmaf(-sv[i], mia[j], acc[i][j]);
                }
        }
#pragma unroll
        for (int i = 0; i < 4; i++) {
            float4 v = make_float4(acc[i][0], acc[i][1], acc[i][2], acc[i][3]);
            *(float4*)(outb + (size_t)(base + 4*tx + i)*C_ + 4*ty) = v;
        }
    }
}

extern "C" void kernel_launch(void* const* d_in, const int* in_sizes, int n_in,
                              void* d_out, int out_size)
{
    const float* inputs = (const float*)d_in[0];
    const float* coords = (const float*)d_in[1];
    const float* wre    = (const float*)d_in[2];
    const float* wim    = (const float*)d_in[3];
    const float* freq   = (const float*)d_in[4];
    float* out = (float*)d_out;

    dim3 grid(CHUNKS, B_);
    pass1_kernel<<<grid, 256>>>(inputs, coords, freq);
    mix_kernel<<<(B_*M_*C_ + 255)/256, 256>>>(wre, wim);
    pass2_kernel<<<grid, 256>>>(coords, freq, out);
}

// round 4
// speedup vs baseline: 2.0293x; 2.0293x over previous
#include <cuda_runtime.h>
#include <cstdint>

#define B_ 8
#define N_ 65536
#define C_ 64
#define M_ 64
#define R_ 32            // conjugate-pair representatives
#define CHUNKS 128
#define PTS (N_/CHUNKS)  // 512 points per block
#define G_ 64            // points staged per group
#define NGROUPS (PTS/G_) // 8
#define SB1 34           // pass1 smem stride in ull (R_ + 2 pad)
#define SB2 33           // pass2 smem stride in ull (R_ + 1 pad)
#define TWO_PI 6.28318530717958647692f

typedef unsigned long long ull;

// ---- scratch (static device globals; no runtime allocation) ----
__device__ ull   g_part[(size_t)B_*CHUNKS*R_*C_];   // packed (sumCos, sumSin) per (b,chunk,r,c)
__device__ float g_MR [(size_t)B_*R_*C_];           // combined real coefficient per rep
__device__ float g_MIn[(size_t)B_*R_*C_];           // combined NEGATED imag coefficient per rep
__device__ int   g_repkx[R_], g_repky[R_], g_mp[R_], g_mm[R_];

// ---- f32x2 helpers ----
__device__ __forceinline__ ull pk2(float lo, float hi) {
    ull r; asm("mov.b64 %0, {%1,%2};" : "=l"(r) : "f"(lo), "f"(hi)); return r;
}
__device__ __forceinline__ void upk2(ull v, float &lo, float &hi) {
    asm("mov.b64 {%0,%1}, %2;" : "=f"(lo), "=f"(hi) : "l"(v));
}
__device__ __forceinline__ void ffma2(ull &d, ull a, ull b) {
    asm("fma.rn.f32x2 %0, %1, %2, %0;" : "+l"(d) : "l"(a), "l"(b));
}

// ---- prep: derive conjugate-pair structure from freq at runtime ----
__global__ void prep_kernel(const float* __restrict__ freq)
{
    __shared__ int skx[M_], sky[M_], keep[M_], part[M_];
    int m = threadIdx.x;
    if (m < M_) {
        skx[m] = __float2int_rn(freq[2*m]);
        sky[m] = __float2int_rn(freq[2*m+1]);
    }
    __syncthreads();
    if (m < M_) {
        int pm = -1;
        for (int m2 = 0; m2 < M_; m2++)
            if (skx[m2] == -skx[m] && sky[m2] == -sky[m]) { pm = m2; break; }
        part[m] = pm;
        keep[m] = (pm < 0 || pm > m) ? 1 : 0;   // representative if unpaired or lower index
    }
    __syncthreads();
    if (m < M_ && keep[m]) {
        int rank = 0;
        for (int m2 = 0; m2 < m; m2++) rank += keep[m2];
        if (rank < R_) {
            g_repkx[rank] = skx[m];
            g_repky[rank] = sky[m];
            g_mp[rank] = m;
            g_mm[rank] = part[m];
        }
    }
}

// ---- basis gen: integer lattice -> powers of e^{i2pi x}, e^{i2pi y} ----
// thread handles point p (0..63 local), rep half h (16 reps); writes packed (cos,sin).
__device__ __forceinline__ void gen_trig(
    const float2* __restrict__ cob, int base, int p, int h,
    const int* __restrict__ skx, const int* __restrict__ sky,
    ull* __restrict__ trigU, int stride)
{
    float2 xy = cob[base + p];
    float sx, cx, sy, cy;
    sincosf(TWO_PI * xy.x, &sx, &cx);
    sincosf(TWO_PI * xy.y, &sy, &cy);
    float pxr[7], pxi[7], pyr[7], pyi[7];
    pxr[0] = 1.f; pxi[0] = 0.f; pyr[0] = 1.f; pyi[0] = 0.f;
#pragma unroll
    for (int k = 1; k < 7; k++) {
        pxr[k] = pxr[k-1]*cx - pxi[k-1]*sx;
        pxi[k] = pxr[k-1]*sx + pxi[k-1]*cx;
        pyr[k] = pyr[k-1]*cy - pyi[k-1]*sy;
        pyi[k] = pyr[k-1]*sy + pyi[k-1]*cy;
    }
#pragma unroll
    for (int j = 0; j < 16; j++) {
        int r = h*16 + j;
        int kx = skx[r], ky = sky[r];
        int ax = kx < 0 ? -kx : kx;
        int ay = ky < 0 ? -ky : ky;
        float xr = pxr[ax], xi = (kx < 0) ? -pxi[ax] : pxi[ax];
        float yr = pyr[ay], yi = (ky < 0) ? -pyi[ay] : pyi[ay];
        float cv = xr*yr - xi*yi;
        float sv = xr*yi + xi*yr;
        trigU[p*stride + r] = pk2(cv, sv);
    }
}

// ---- Pass 1: partial (sumCos, sumSin)[r][c] over this block's points ----
// block 128 = txr(8)*4 reps  x  ty(16)*4 channels
__global__ void __launch_bounds__(128) pass1_kernel(
    const float* __restrict__ inputs,
    const float* __restrict__ coords)
{
    __shared__ ull trigU[G_*SB1];
    __shared__ int skx[R_], sky[R_];

    int b = blockIdx.y, chunk = blockIdx.x;
    int tid = threadIdx.x;
    int txr = tid & 7, ty = tid >> 3;
    if (tid < R_) { skx[tid] = g_repkx[tid]; sky[tid] = g_repky[tid]; }

    ull acc[4][4];
#pragma unroll
    for (int j = 0; j < 4; j++)
#pragma unroll
        for (int c = 0; c < 4; c++) acc[j][c] = 0ull;

    const float* inb = inputs + (size_t)b*N_*C_;
    const float2* cob = (const float2*)(coords + (size_t)b*N_*2);
    int n0 = chunk * PTS;
    int gp = tid & 63, gh = tid >> 6;

    for (int g = 0; g < NGROUPS; g++) {
        int base = n0 + g*G_;
        __syncthreads();
        gen_trig(cob, base, gp, gh, skx, sky, trigU, SB1);
        __syncthreads();
#pragma unroll 2
        for (int p = 0; p < G_; p++) {
            float4 xf = *(const float4*)(inb + (size_t)(base + p)*C_ + 4*ty);
            ull d0 = pk2(xf.x, xf.x), d1 = pk2(xf.y, xf.y);
            ull d2 = pk2(xf.z, xf.z), d3 = pk2(xf.w, xf.w);
            const ull* tp = &trigU[p*SB1 + 4*txr];
            ulonglong2 tA = *(const ulonglong2*)tp;
            ulonglong2 tB = *(const ulonglong2*)(tp + 2);
            ull t[4] = {tA.x, tA.y, tB.x, tB.y};
#pragma unroll
            for (int j = 0; j < 4; j++) {
                ffma2(acc[j][0], t[j], d0);
                ffma2(acc[j][1], t[j], d1);
                ffma2(acc[j][2], t[j], d2);
                ffma2(acc[j][3], t[j], d3);
            }
        }
    }

    ull* pc = g_part + (size_t)(b*CHUNKS + chunk)*R_*C_;
#pragma unroll
    for (int j = 0; j < 4; j++) {
        int r = 4*txr + j;
        ulonglong2 s0; s0.x = acc[j][0]; s0.y = acc[j][1];
        ulonglong2 s1; s1.x = acc[j][2]; s1.y = acc[j][3];
        *(ulonglong2*)&pc[r*C_ + 4*ty]     = s0;
        *(ulonglong2*)&pc[r*C_ + 4*ty + 2] = s1;
    }
}

// ---- Mix: reduce chunks, normalize, apply complex weight, fold pairs ----
__global__ void mix_kernel(const float* __restrict__ wre, const float* __restrict__ wim)
{
    int idx = blockIdx.x*blockDim.x + threadIdx.x;
    if (idx >= B_*R_*C_) return;
    int c = idx & (C_-1);
    int r = (idx >> 6) & (R_-1);
    int b = idx >> 11;

    const ull* p = g_part + (size_t)b*CHUNKS*R_*C_ + r*C_ + c;
    float sc = 0.f, ss = 0.f;
#pragma unroll 4
    for (int k = 0; k < CHUNKS; k++) {
        float lo, hi; upk2(p[(size_t)k*R_*C_], lo, hi);
        sc += lo; ss += hi;
    }
    const float invN = 1.0f / (float)N_;
    float re = sc * invN, im = -ss * invN;   // coeff of representative mode

    float MR = 0.f, MIn = 0.f;
    int mp = g_mp[r];
    if (mp >= 0) {
        float wrP = wre[mp*C_ + c], wiP = wim[mp*C_ + c];
        float ReP = re*wrP - im*wiP;
        float ImP = re*wiP + im*wrP;
        int mm = g_mm[r];
        if (mm >= 0) {
            // coeff of negated mode = conj(coeff) = (re, -im)
            float wrM = wre[mm*C_ + c], wiM = wim[mm*C_ + c];
            float ReM = re*wrM + im*wiM;
            float ImM = re*wiM - im*wrM;
            MR  = ReP + ReM;
            MIn = -(ImP - ImM);
        } else {
            MR  = ReP;
            MIn = -ImP;
        }
    }
    g_MR [(size_t)(b*R_ + r)*C_ + c] = MR;
    g_MIn[(size_t)(b*R_ + r)*C_ + c] = MIn;
}

// ---- Pass 2: out[n][c] = sum_r cos*MR + sin*MIn ----
// block 128 = tx(16)*4 points  x  ty(8)*8 channels
__global__ void __launch_bounds__(128) pass2_kernel(
    const float* __restrict__ coords,
    float* __restrict__ out)
{
    __shared__ ull trigU[G_*SB2];
    __shared__ int skx[R_], sky[R_];

    int b = blockIdx.y, chunk = blockIdx.x;
    int tid = threadIdx.x;
    int tx = tid & 15, ty = tid >> 4;
    if (tid < R_) { skx[tid] = g_repkx[tid]; sky[tid] = g_repky[tid]; }

    const float2* cob = (const float2*)(coords + (size_t)b*N_*2);
    const float* MRb  = g_MR  + (size_t)b*R_*C_;
    const float* MInb = g_MIn + (size_t)b*R_*C_;
    float* outb = out + (size_t)b*N_*C_;
    int n0 = chunk * PTS;
    int gp = tid & 63, gh = tid >> 6;

    for (int g = 0; g < NGROUPS; g++) {
        int base = n0 + g*G_;
        __syncthreads();
        gen_trig(cob, base, gp, gh, skx, sky, trigU, SB2);
        __syncthreads();

        ull acc[4][4];
#pragma unroll
        for (int pi = 0; pi < 4; pi++)
#pragma unroll
            for (int u = 0; u < 4; u++) acc[pi][u] = 0ull;

#pragma unroll 2
        for (int r = 0; r < R_; r++) {
            const ull* mr4 = (const ull*)(MRb  + r*C_ + 8*ty);
            const ull* mi4 = (const ull*)(MInb + r*C_ + 8*ty);
            ulonglong2 mrA = *(const ulonglong2*)mr4;
            ulonglong2 mrB = *(const ulonglong2*)(mr4 + 2);
            ulonglong2 miA = *(const ulonglong2*)mi4;
            ulonglong2 miB = *(const ulonglong2*)(mi4 + 2);
            ull MRu[4] = {mrA.x, mrA.y, mrB.x, mrB.y};
            ull MIu[4] = {miA.x, miA.y, miB.x, miB.y};
#pragma unroll
            for (int pi = 0; pi < 4; pi++) {
                ull pr = trigU[(pi*16 + tx)*SB2 + r];
                float cv, sv; upk2(pr, cv, sv);
                ull dc = pk2(cv, cv), ds = pk2(sv, sv);
#pragma unroll
                for (int u = 0; u < 4; u++) {
                    ffma2(acc[pi][u], dc, MRu[u]);
                    ffma2(acc[pi][u], ds, MIu[u]);
                }
            }
        }

#pragma unroll
        for (int pi = 0; pi < 4; pi++) {
            int n = base + pi*16 + tx;
            ull* op = (ull*)(outb + (size_t)n*C_ + 8*ty);
            ulonglong2 s0; s0.x = acc[pi][0]; s0.y = acc[pi][1];
            ulonglong2 s1; s1.x = acc[pi][2]; s1.y = acc[pi][3];
            *(ulonglong2*)op       = s0;
            *(ulonglong2*)(op + 2) = s1;
        }
    }
}

extern "C" void kernel_launch(void* const* d_in, const int* in_sizes, int n_in,
                              void* d_out, int out_size)
{
    const float* inputs = (const float*)d_in[0];
    const float* coords = (const float*)d_in[1];
    const float* wre    = (const float*)d_in[2];
    const float* wim    = (const float*)d_in[3];
    const float* freq   = (const float*)d_in[4];
    float* out = (float*)d_out;

    prep_kernel<<<1, 64>>>(freq);
    dim3 grid(CHUNKS, B_);
    pass1_kernel<<<grid, 128>>>(inputs, coords);
    mix_kernel<<<(B_*R_*C_ + 255)/256, 256>>>(wre, wim);
    pass2_kernel<<<grid, 128>>>(coords, out);
}

// round 8
// speedup vs baseline: 2.5020x; 1.2329x over previous
#include <cuda_runtime.h>
#include <cstdint>

#define B_ 8
#define N_ 65536
#define C_ 64
#define M_ 64
#define R_ 32            // conjugate-pair representatives
#define CHUNKS 128
#define PTS (N_/CHUNKS)  // 512 points per block
#define G_ 64            // points staged per group
#define NGROUPS (PTS/G_) // 8
#define SB1 34           // pass1 trig stride in ull ([point][rep])
#define ST2 66           // pass2 trig stride in ull ([rep][point])
#define TWO_PI 6.28318530717958647692f

typedef unsigned long long ull;

// ---- scratch (static device globals; no runtime allocation) ----
__device__ ull   g_part[(size_t)B_*CHUNKS*R_*C_];   // packed (sumCos, sumSin)
__device__ float g_MR [(size_t)B_*R_*C_];           // combined real coefficient
__device__ float g_MIn[(size_t)B_*R_*C_];           // combined negated imag coefficient
__device__ int   g_repkx[R_], g_repky[R_], g_mp[R_], g_mm[R_];

// ---- f32x2 helpers ----
__device__ __forceinline__ ull pk2(float lo, float hi) {
    ull r; asm("mov.b64 %0, {%1,%2};" : "=l"(r) : "f"(lo), "f"(hi)); return r;
}
__device__ __forceinline__ void upk2(ull v, float &lo, float &hi) {
    asm("mov.b64 {%0,%1}, %2;" : "=f"(lo), "=f"(hi) : "l"(v));
}
__device__ __forceinline__ void ffma2(ull &d, ull a, ull b) {
    asm("fma.rn.f32x2 %0, %1, %2, %0;" : "+l"(d) : "l"(a), "l"(b));
}

// ---- cp.async helpers ----
__device__ __forceinline__ uint32_t smem_u32(const void* p) {
    return (uint32_t)__cvta_generic_to_shared(p);
}
__device__ __forceinline__ void cp_async16(uint32_t saddr, const void* gaddr) {
    asm volatile("cp.async.cg.shared.global [%0], [%1], 16;" :: "r"(saddr), "l"(gaddr));
}
__device__ __forceinline__ void cp_commit() {
    asm volatile("cp.async.commit_group;" ::: "memory");
}
template<int n> __device__ __forceinline__ void cp_wait() {
    asm volatile("cp.async.wait_group %0;" :: "n"(n) : "memory");
}

// ---- prep: derive conjugate-pair structure from freq at runtime ----
__global__ void prep_kernel(const float* __restrict__ freq)
{
    __shared__ int skx[M_], sky[M_], keep[M_], part[M_];
    int m = threadIdx.x;
    if (m < M_) {
        skx[m] = __float2int_rn(freq[2*m]);
        sky[m] = __float2int_rn(freq[2*m+1]);
    }
    __syncthreads();
    if (m < M_) {
        int pm = -1;
        for (int m2 = 0; m2 < M_; m2++)
            if (skx[m2] == -skx[m] && sky[m2] == -sky[m]) { pm = m2; break; }
        part[m] = pm;
        keep[m] = (pm < 0 || pm > m) ? 1 : 0;
    }
    __syncthreads();
    if (m < M_ && keep[m]) {
        int rank = 0;
        for (int m2 = 0; m2 < m; m2++) rank += keep[m2];
        if (rank < R_) {
            g_repkx[rank] = skx[m];
            g_repky[rank] = sky[m];
            g_mp[rank] = m;
            g_mm[rank] = part[m];
        }
    }
}

// ---- basis gen core: integer lattice -> powers of e^{i2pi x}, e^{i2pi y} ----
// Computes packed (cos,sin) for 16 reps (half h) of point p; layout chosen by caller.
template<bool TRANSPOSED>
__device__ __forceinline__ void gen_trig(
    const float2* __restrict__ cob, int base, int p, int h,
    const int* __restrict__ skx, const int* __restrict__ sky,
    ull* __restrict__ trig, int stride)
{
    float2 xy = cob[base + p];
    float sx, cx, sy, cy;
    sincosf(TWO_PI * xy.x, &sx, &cx);
    sincosf(TWO_PI * xy.y, &sy, &cy);
    float pxr[7], pxi[7], pyr[7], pyi[7];
    pxr[0] = 1.f; pxi[0] = 0.f; pyr[0] = 1.f; pyi[0] = 0.f;
#pragma unroll
    for (int k = 1; k < 7; k++) {
        pxr[k] = pxr[k-1]*cx - pxi[k-1]*sx;
        pxi[k] = pxr[k-1]*sx + pxi[k-1]*cx;
        pyr[k] = pyr[k-1]*cy - pyi[k-1]*sy;
        pyi[k] = pyr[k-1]*sy + pyi[k-1]*cy;
    }
#pragma unroll
    for (int j = 0; j < 16; j++) {
        int r = h*16 + j;
        int kx = skx[r], ky = sky[r];
        int ax = kx < 0 ? -kx : kx;
        int ay = ky < 0 ? -ky : ky;
        float xr = pxr[ax], xi = (kx < 0) ? -pxi[ax] : pxi[ax];
        float yr = pyr[ay], yi = (ky < 0) ? -pyi[ay] : pyi[ay];
        float cv = xr*yr - xi*yi;
        float sv = xr*yi + xi*yr;
        if (TRANSPOSED) trig[r*stride + p] = pk2(cv, sv);
        else            trig[p*stride + r] = pk2(cv, sv);
    }
}

// ---- Pass 1: partial (sumCos, sumSin)[r][c]; cp.async double-buffered inputs ----
// block 128 = txr(8)*4 reps x ty(16)*4 channels
__global__ void __launch_bounds__(128) pass1_kernel(
    const float* __restrict__ inputs,
    const float* __restrict__ coords)
{
    __shared__ float xbuf[2][G_*C_];   // 2 x 16 KB staged input tiles
    __shared__ ull trigU[G_*SB1];      // [point][rep]
    __shared__ int skx[R_], sky[R_];

    int b = blockIdx.y, chunk = blockIdx.x;
    int tid = threadIdx.x;
    int txr = tid & 7, ty = tid >> 3;
    if (tid < R_) { skx[tid] = g_repkx[tid]; sky[tid] = g_repky[tid]; }

    ull acc[4][4];
#pragma unroll
    for (int j = 0; j < 4; j++)
#pragma unroll
        for (int c = 0; c < 4; c++) acc[j][c] = 0ull;

    const float* inb = inputs + (size_t)b*N_*C_;
    const float2* cob = (const float2*)(coords + (size_t)b*N_*2);
    int n0 = chunk * PTS;
    int gp = tid & 63, gh = tid >> 6;

    // prologue: stage group 0 (contiguous 16 KB slab)
    {
        const float4* src = (const float4*)(inb + (size_t)n0*C_);
        float4* dst = (float4*)xbuf[0];
#pragma unroll
        for (int i = 0; i < 8; i++) {
            int f = tid + i*128;
            cp_async16(smem_u32(dst + f), src + f);
        }
    }
    cp_commit();

    for (int g = 0; g < NGROUPS; g++) {
        int base = n0 + g*G_;
        __syncthreads();   // prior compute done with trigU and xbuf[(g+1)&1]
        if (g + 1 < NGROUPS) {
            const float4* src = (const float4*)(inb + (size_t)(base + G_)*C_);
            float4* dst = (float4*)xbuf[(g+1)&1];
#pragma unroll
            for (int i = 0; i < 8; i++) {
                int f = tid + i*128;
                cp_async16(smem_u32(dst + f), src + f);
            }
        }
        cp_commit();
        gen_trig<false>(cob, base, gp, gh, skx, sky, trigU, SB1);
        cp_wait<1>();      // group g data resident
        __syncthreads();

        const float* xb = xbuf[g&1];
#pragma unroll 4
        for (int p = 0; p < G_; p++) {
            float4 xf = *(const float4*)(xb + p*C_ + 4*ty);
            ull d0 = pk2(xf.x, xf.x), d1 = pk2(xf.y, xf.y);
            ull d2 = pk2(xf.z, xf.z), d3 = pk2(xf.w, xf.w);
            const ull* tp = &trigU[p*SB1 + 4*txr];
            ulonglong2 tA = *(const ulonglong2*)tp;
            ulonglong2 tB = *(const ulonglong2*)(tp + 2);
            ull t[4] = {tA.x, tA.y, tB.x, tB.y};
#pragma unroll
            for (int j = 0; j < 4; j++) {
                ffma2(acc[j][0], t[j], d0);
                ffma2(acc[j][1], t[j], d1);
                ffma2(acc[j][2], t[j], d2);
                ffma2(acc[j][3], t[j], d3);
            }
        }
    }

    ull* pc = g_part + (size_t)(b*CHUNKS + chunk)*R_*C_;
#pragma unroll
    for (int j = 0; j < 4; j++) {
        int r = 4*txr + j;
        ulonglong2 s0; s0.x = acc[j][0]; s0.y = acc[j][1];
        ulonglong2 s1; s1.x = acc[j][2]; s1.y = acc[j][3];
        *(ulonglong2*)&pc[r*C_ + 4*ty]     = s0;
        *(ulonglong2*)&pc[r*C_ + 4*ty + 2] = s1;
    }
}

// ---- Mix: reduce chunks, normalize, apply complex weight, fold pairs ----
__global__ void mix_kernel(const float* __restrict__ wre, const float* __restrict__ wim)
{
    int idx = blockIdx.x*blockDim.x + threadIdx.x;
    if (idx >= B_*R_*C_) return;
    int c = idx & (C_-1);
    int r = (idx >> 6) & (R_-1);
    int b = idx >> 11;

    const ull* p = g_part + (size_t)b*CHUNKS*R_*C_ + r*C_ + c;
    float sc = 0.f, ss = 0.f;
#pragma unroll 4
    for (int k = 0; k < CHUNKS; k++) {
        float lo, hi; upk2(p[(size_t)k*R_*C_], lo, hi);
        sc += lo; ss += hi;
    }
    const float invN = 1.0f / (float)N_;
    float re = sc * invN, im = -ss * invN;

    float MR = 0.f, MIn = 0.f;
    int mp = g_mp[r];
    if (mp >= 0) {
        float wrP = wre[mp*C_ + c], wiP = wim[mp*C_ + c];
        float ReP = re*wrP - im*wiP;
        float ImP = re*wiP + im*wrP;
        int mm = g_mm[r];
        if (mm >= 0) {
            float wrM = wre[mm*C_ + c], wiM = wim[mm*C_ + c];
            float ReM = re*wrM + im*wiM;
            float ImM = re*wiM - im*wrM;
            MR  = ReP + ReM;
            MIn = -(ImP - ImM);
        } else {
            MR  = ReP;
            MIn = -ImP;
        }
    }
    g_MR [(size_t)(b*R_ + r)*C_ + c] = MR;
    g_MIn[(size_t)(b*R_ + r)*C_ + c] = MIn;
}

// ---- Pass 2: out[n][c] = sum_r cos*MR + sin*MIn ----
// block 128 = tx(16) x 4 CONSECUTIVE points  x  ty(8) x 8 channels
// MR/MI staged in shared once per block; trig transposed [r][point].
__global__ void __launch_bounds__(128) pass2_kernel(
    const float* __restrict__ coords,
    float* __restrict__ out)
{
    __shared__ ull sMR[R_*32];        // [r][cpair] 8 KB
    __shared__ ull sMI[R_*32];        // 8 KB
    __shared__ ull trigT[R_*ST2];     // [r][point] 16.9 KB
    __shared__ int skx[R_], sky[R_];

    int b = blockIdx.y, chunk = blockIdx.x;
    int tid = threadIdx.x;
    int tx = tid & 15, ty = tid >> 4;
    if (tid < R_) { skx[tid] = g_repkx[tid]; sky[tid] = g_repky[tid]; }

    // stage MR / MIn (16 KB total, once per block)
    {
        const ull* gMR = (const ull*)(g_MR  + (size_t)b*R_*C_);
        const ull* gMI = (const ull*)(g_MIn + (size_t)b*R_*C_);
#pragma unroll
        for (int i = 0; i < (R_*32)/128; i++) {
            int f = tid + i*128;
            sMR[f] = gMR[f];
            sMI[f] = gMI[f];
        }
    }

    const float2* cob = (const float2*)(coords + (size_t)b*N_*2);
    float* outb = out + (size_t)b*N_*C_;
    int n0 = chunk * PTS;
    int gp = tid & 63, gh = tid >> 6;

    for (int g = 0; g < NGROUPS; g++) {
        int base = n0 + g*G_;
        __syncthreads();   // covers MR staging (first iter) and trig reuse
        gen_trig<true>(cob, base, gp, gh, skx, sky, trigT, ST2);
        __syncthreads();

        ull acc[4][4];
#pragma unroll
        for (int i = 0; i < 4; i++)
#pragma unroll
            for (int u = 0; u < 4; u++) acc[i][u] = 0ull;

#pragma unroll 2
        for (int r = 0; r < R_; r++) {
            ulonglong2 mA = *(const ulonglong2*)&sMR[r*32 + 4*ty];
            ulonglong2 mB = *(const ulonglong2*)&sMR[r*32 + 4*ty + 2];
            ulonglong2 iA = *(const ulonglong2*)&sMI[r*32 + 4*ty];
            ulonglong2 iB = *(const ulonglong2*)&sMI[r*32 + 4*ty + 2];
            ull MRu[4] = {mA.x, mA.y, mB.x, mB.y};
            ull MIu[4] = {iA.x, iA.y, iB.x, iB.y};
            ulonglong2 tA = *(const ulonglong2*)&trigT[r*ST2 + 4*tx];
            ulonglong2 tB = *(const ulonglong2*)&trigT[r*ST2 + 4*tx + 2];
            ull t[4] = {tA.x, tA.y, tB.x, tB.y};
#pragma unroll
            for (int i = 0; i < 4; i++) {
                float cv, sv; upk2(t[i], cv, sv);
                ull dc = pk2(cv, cv), ds = pk2(sv, sv);
#pragma unroll
                for (int u = 0; u < 4; u++) {
                    ffma2(acc[i][u], dc, MRu[u]);
                    ffma2(acc[i][u], ds, MIu[u]);
                }
            }
        }

#pragma unroll
        for (int i = 0; i < 4; i++) {
            int n = base + 4*tx + i;
            ull* op = (ull*)(outb + (size_t)n*C_ + 8*ty);
            ulonglong2 s0; s0.x = acc[i][0]; s0.y = acc[i][1];
            ulonglong2 s1; s1.x = acc[i][2]; s1.y = acc[i][3];
            *(ulonglong2*)op       = s0;
            *(ulonglong2*)(op + 2) = s1;
        }
    }
}

extern "C" void kernel_launch(void* const* d_in, const int* in_sizes, int n_in,
                              void* d_out, int out_size)
{
    const float* inputs = (const float*)d_in[0];
    const float* coords = (const float*)d_in[1];
    const float* wre    = (const float*)d_in[2];
    const float* wim    = (const float*)d_in[3];
    const float* freq   = (const float*)d_in[4];
    float* out = (float*)d_out;

    prep_kernel<<<1, 64>>>(freq);
    dim3 grid(CHUNKS, B_);
    pass1_kernel<<<grid, 128>>>(inputs, coords);
    mix_kernel<<<(B_*R_*C_ + 255)/256, 256>>>(wre, wim);
    pass2_kernel<<<grid, 128>>>(coords, out);
}